// round 5
// baseline (speedup 1.0000x reference)
#include <cuda_runtime.h>
#include <cstdint>
#include <cstddef>

// ---------------------------------------------------------------------------
// Covariance:  cov[b] = (X^T X)/N - mu mu^T, packed upper triangle.
// X: [64, 4096, 256] f32 -> out: [64, 32896] f32
// mma.sync m16n8k8 TF32 SYRK, triangle-only tiling:
//   warp-tile = 64(m) x 16(n); triangle = 40 tiles; 2 CTAs/batch x 20 tiles;
//   8 warps/CTA, slots {w, w+8, 16+w if w<4} -> 5 tiles per SMSP (balanced).
// Staging (cvt.rna + STS) interleaved into the MMA k-steps (prev-chunk bubble
// elimination); double-buffered SMEM tile [32 k][256 d] at row stride 264.
// ---------------------------------------------------------------------------

static constexpr int BATCH  = 64;
static constexpr int NPTS   = 4096;
static constexpr int DIM    = 256;
static constexpr int TRI    = DIM * (DIM + 1) / 2;   // 32896
static constexpr int KC     = 32;                    // K per chunk
static constexpr int NCHUNK = NPTS / KC;             // 128
static constexpr int SROW   = 264;                   // smem floats per k-row
static constexpr int STAGE_F = KC * SROW;            // 8448 floats
static constexpr int SMEM_FLOATS = 2 * STAGE_F + 4 * 256 + 256;
static constexpr int SMEM_BYTES  = SMEM_FLOATS * 4;  // 72704

#define MMA_TF32(ac, A, b0, b1)                                                 \
    asm volatile(                                                               \
        "mma.sync.aligned.m16n8k8.row.col.f32.tf32.tf32.f32 "                   \
        "{%0,%1,%2,%3}, {%4,%5,%6,%7}, {%8,%9}, {%0,%1,%2,%3};"                 \
        : "+f"((ac)[0]), "+f"((ac)[1]), "+f"((ac)[2]), "+f"((ac)[3])            \
        : "r"((A)[0]), "r"((A)[1]), "r"((A)[2]), "r"((A)[3]),                   \
          "r"(b0), "r"(b1))

static __device__ __forceinline__ uint32_t cvt_rna_tf32(float v) {
    uint32_t r;
    asm("cvt.rna.tf32.f32 %0, %1;" : "=r"(r) : "f"(v));
    return r;
}

// tile id -> (mi, ni): triangle tiles, m-granularity 64, n-granularity 16.
static __device__ __forceinline__ void tile_mn(int t, int& mi, int& ni) {
    if (t < 16)      { mi = 0; ni = t; }
    else if (t < 28) { mi = 1; ni = t - 16 + 4; }
    else if (t < 36) { mi = 2; ni = t - 28 + 8; }
    else             { mi = 3; ni = t - 36 + 12; }
}

__global__ void __launch_bounds__(256, 1)
cov_mma_kernel(const float* __restrict__ X, float* __restrict__ out)
{
    extern __shared__ float sm[];
    float* buf0 = sm;
    float* buf1 = sm + STAGE_F;
    float* psum = sm + 2 * STAGE_F;        // [4][256]
    float* csum = psum + 4 * 256;          // [256]

    const int tid  = threadIdx.x;
    const int lane = tid & 31;
    const int wid  = tid >> 5;
    const int b    = blockIdx.x >> 1;
    const int h    = blockIdx.x & 1;       // tile-half
    const int g    = lane >> 2;            // 0..7
    const int tig  = lane & 3;             // 0..3

    // ---- warp tile assignment: up to 3 tiles of 64(m) x 16(n) ----
    int tm[3], tn[3];
    const int nt = (wid < 4) ? 3 : 2;
    {
        int id0 = 20 * h + wid;
        int id1 = 20 * h + wid + 8;
        tile_mn(id0, tm[0], tn[0]);
        tile_mn(id1, tm[1], tn[1]);
        if (wid < 4) { tile_mn(20 * h + 16 + wid, tm[2], tn[2]); }
        else         { tm[2] = tm[1]; tn[2] = tn[1]; }   // unused
    }

    // staging: thread t owns float4 lane t within each 2048-float4 chunk
    const float4* gp =
        reinterpret_cast<const float4*>(X + (size_t)b * NPTS * DIM) + tid;
    const int dq    = (tid & 63) * 4;      // fixed d-quad
    const int krow0 = tid >> 6;            // rows krow0 + 4j

    float acc[3][8][4] = {};               // [tile][mf*2+nf][c]
    float s4[4] = {0.f, 0.f, 0.f, 0.f};
    float4 v[8];

#define STAGE_GROUP(dst, j) do {                                                \
        uint32_t r0 = cvt_rna_tf32(v[j].x), r1 = cvt_rna_tf32(v[j].y);          \
        uint32_t r2 = cvt_rna_tf32(v[j].z), r3 = cvt_rna_tf32(v[j].w);          \
        s4[0] += __uint_as_float(r0); s4[1] += __uint_as_float(r1);             \
        s4[2] += __uint_as_float(r2); s4[3] += __uint_as_float(r3);             \
        *reinterpret_cast<float4*>(&(dst)[(krow0 + 4 * (j)) * SROW + dq]) =     \
            make_float4(__uint_as_float(r0), __uint_as_float(r1),               \
                        __uint_as_float(r2), __uint_as_float(r3));              \
    } while (0)

    // ---- prologue: stage chunk 0 ----
#pragma unroll
    for (int j = 0; j < 8; ++j) v[j] = gp[j * 256];
#pragma unroll
    for (int j = 0; j < 8; ++j) STAGE_GROUP(buf0, j);
    __syncthreads();

#pragma unroll 1
    for (int c = 0; c < NCHUNK; ++c) {
        const bool more = (c + 1 < NCHUNK);
        const uint32_t* cur =
            reinterpret_cast<const uint32_t*>((c & 1) ? buf1 : buf0);
        float* nxt = (c & 1) ? buf0 : buf1;

        if (more) {
#pragma unroll
            for (int j = 0; j < 8; ++j)
                v[j] = gp[(c + 1) * 2048 + j * 256];
        }

#pragma unroll
        for (int ks = 0; ks < 4; ++ks) {
            const int k0 = ks * 8;
#pragma unroll
            for (int t = 0; t < 3; ++t) {
                if (t >= nt) break;
                const int m00 = tm[t] * 64 + g;
                const int n00 = tn[t] * 16 + g;
                uint32_t bf[2][2];
#pragma unroll
                for (int nf = 0; nf < 2; ++nf) {
                    const int n0 = n00 + nf * 8;
                    bf[nf][0] = cur[(k0 + tig)     * SROW + n0];
                    bf[nf][1] = cur[(k0 + tig + 4) * SROW + n0];
                }
#pragma unroll
                for (int mf = 0; mf < 4; ++mf) {
                    const int m0 = m00 + mf * 16;
                    uint32_t af[4];
                    af[0] = cur[(k0 + tig)     * SROW + m0];
                    af[1] = cur[(k0 + tig)     * SROW + m0 + 8];
                    af[2] = cur[(k0 + tig + 4) * SROW + m0];
                    af[3] = cur[(k0 + tig + 4) * SROW + m0 + 8];
                    MMA_TF32(acc[t][mf * 2 + 0], af, bf[0][0], bf[0][1]);
                    MMA_TF32(acc[t][mf * 2 + 1], af, bf[1][0], bf[1][1]);
                }
            }
            // interleave staging of next chunk (2 of 8 groups per k-step)
            if (more) {
                STAGE_GROUP(nxt, 2 * ks + 0);
                STAGE_GROUP(nxt, 2 * ks + 1);
            }
        }
        __syncthreads();
    }

    // ---- column-sum reduction ----
    psum[(tid >> 6) * 256 + dq + 0] = s4[0];
    psum[(tid >> 6) * 256 + dq + 1] = s4[1];
    psum[(tid >> 6) * 256 + dq + 2] = s4[2];
    psum[(tid >> 6) * 256 + dq + 3] = s4[3];
    __syncthreads();
    csum[tid] = psum[tid] + psum[256 + tid] + psum[512 + tid] + psum[768 + tid];
    __syncthreads();

    // ---- epilogue: cov = acc/N - mu_d mu_e, packed upper triangle ----
    const float invN = 1.0f / (float)NPTS;
    const size_t outb = (size_t)b * TRI;

#pragma unroll
    for (int t = 0; t < 3; ++t) {
        if (t >= nt) break;
#pragma unroll
        for (int mf = 0; mf < 4; ++mf) {
#pragma unroll
            for (int nf = 0; nf < 2; ++nf) {
#pragma unroll
                for (int cc = 0; cc < 4; ++cc) {
                    const int d = tm[t] * 64 + mf * 16 + g + (cc >> 1) * 8;
                    const int e = tn[t] * 16 + nf * 8 + 2 * tig + (cc & 1);
                    if (e >= d) {
                        const float mu_d = csum[d] * invN;
                        const float mu_e = csum[e] * invN;
                        const int idx = d * DIM - (d * (d - 1)) / 2 - d + e;
                        out[outb + (size_t)idx] =
                            acc[t][mf * 2 + nf][cc] * invN - mu_d * mu_e;
                    }
                }
            }
        }
    }
}

extern "C" void kernel_launch(void* const* d_in, const int* in_sizes, int n_in,
                              void* d_out, int out_size)
{
    const float* X = (const float*)d_in[0];
    float* out = (float*)d_out;
    cudaFuncSetAttribute(cov_mma_kernel,
                         cudaFuncAttributeMaxDynamicSharedMemorySize,
                         SMEM_BYTES);
    cov_mma_kernel<<<BATCH * 2, 256, SMEM_BYTES>>>(X, out);
}

// round 7
// speedup vs baseline: 1.3281x; 1.3281x over previous
#include <cuda_runtime.h>
#include <cstdint>
#include <cstddef>

// ---------------------------------------------------------------------------
// Covariance:  cov[b] = (X^T X)/N - mu mu^T, packed upper triangle.
// X: [64, 4096, 256] f32 -> out: [64, 32896] f32
// TF32 mma.sync m16n8k8 SYRK, triangle-only:
//   half-tile = 64(m) x 32(n); 20 half-tiles/batch (nj >= 2*mi), 10 per CTA.
//   Warp w owns HT[2w+h] (4 k-steps); HT[16+h]/HT[18+h] k-split across groups.
//   => 10 units/SMSP/chunk (unit = 16 MMAs) = 1280 cyc MMA floor,
//      960 LDS crossbar cyc (24 LDS / unit). Warp groups staggered.
// ---------------------------------------------------------------------------

static constexpr int BATCH  = 64;
static constexpr int NPTS   = 4096;
static constexpr int DIM    = 256;
static constexpr int TRI    = DIM * (DIM + 1) / 2;   // 32896
static constexpr int KC     = 32;
static constexpr int NCHUNK = NPTS / KC;             // 128
static constexpr int SROW   = 264;                   // 264 % 32 == 8 -> conflict-free
static constexpr int STAGE_F = KC * SROW;            // 8448 floats
static constexpr int SMEM_FLOATS = 2 * STAGE_F + 4 * 256 + 256;
static constexpr int SMEM_BYTES  = SMEM_FLOATS * 4;  // 72704

#define MMA_TF32(ac, A, b0, b1)                                                 \
    asm volatile(                                                               \
        "mma.sync.aligned.m16n8k8.row.col.f32.tf32.tf32.f32 "                   \
        "{%0,%1,%2,%3}, {%4,%5,%6,%7}, {%8,%9}, {%0,%1,%2,%3};"                 \
        : "+f"((ac)[0]), "+f"((ac)[1]), "+f"((ac)[2]), "+f"((ac)[3])            \
        : "r"((A)[0]), "r"((A)[1]), "r"((A)[2]), "r"((A)[3]),                   \
          "r"(b0), "r"(b1))

static __device__ __forceinline__ uint32_t cvt_rna_tf32(float v) {
    uint32_t r;
    asm("cvt.rna.tf32.f32 %0, %1;" : "=r"(r) : "f"(v));
    return r;
}

// half-tile id (0..19) -> (mi in 0..3 of 64 rows, nj in 0..7 of 32 cols)
static __device__ __forceinline__ void ht_mn(int t, int& mi, int& nj) {
    if (t < 8)       { mi = 0; nj = t; }
    else if (t < 14) { mi = 1; nj = t - 6; }
    else if (t < 18) { mi = 2; nj = t - 10; }
    else             { mi = 3; nj = t - 12; }
}

// one unit: 64x32 half-tile at one k-step (8 k) -> 16 MMAs, 24 LDS
static __device__ __forceinline__ void unit_mma(
    const uint32_t* __restrict__ cur, int mbase, int nbase, int k0,
    float (&acc)[16][4], int g, int tig)
{
    uint32_t bf[4][2];
#pragma unroll
    for (int nf = 0; nf < 4; ++nf) {
        const int n0 = nbase + nf * 8 + g;
        bf[nf][0] = cur[(k0 + tig)     * SROW + n0];
        bf[nf][1] = cur[(k0 + tig + 4) * SROW + n0];
    }
#pragma unroll
    for (int mf = 0; mf < 4; ++mf) {
        const int m0 = mbase + mf * 16 + g;
        uint32_t af[4];
        af[0] = cur[(k0 + tig)     * SROW + m0];
        af[1] = cur[(k0 + tig)     * SROW + m0 + 8];
        af[2] = cur[(k0 + tig + 4) * SROW + m0];
        af[3] = cur[(k0 + tig + 4) * SROW + m0 + 8];
#pragma unroll
        for (int nf = 0; nf < 4; ++nf)
            MMA_TF32(acc[mf * 4 + nf], af, bf[nf][0], bf[nf][1]);
    }
}

__global__ void __launch_bounds__(256, 1)
cov_mma_kernel(const float* __restrict__ X, float* __restrict__ out)
{
    extern __shared__ float sm[];
    float* buf0 = sm;
    float* buf1 = sm + STAGE_F;
    float* psum = sm + 2 * STAGE_F;        // [4][256]
    float* csum = psum + 4 * 256;          // [256]

    const int tid  = threadIdx.x;
    const int lane = tid & 31;
    const int wid  = tid >> 5;
    const int b    = blockIdx.x >> 1;
    const int h    = blockIdx.x & 1;
    const int g    = lane >> 2;
    const int tig  = lane & 3;

    // tile assignment: CTA h takes half-tiles 2*i + h, i = 0..9
    int own_mi, own_nj, sh_mi, sh_nj;
    ht_mn(2 * wid + h, own_mi, own_nj);
    ht_mn(2 * (8 + (wid >> 2)) + h, sh_mi, sh_nj);
    const int own_m = own_mi * 64, own_n = own_nj * 32;
    const int sh_m  = sh_mi * 64,  sh_n  = sh_nj * 32;
    const int sh_k0 = (wid & 3) * 8;

    // staging: thread t owns float4 lane t within each 2048-float4 chunk
    const float4* gp =
        reinterpret_cast<const float4*>(X + (size_t)b * NPTS * DIM) + tid;
    const int dq    = (tid & 63) * 4;
    const int krow0 = tid >> 6;

    float acc0[16][4] = {};                // own half-tile
    float acc1[16][4] = {};                // shared half-tile (one k-step)
    float s4[4] = {0.f, 0.f, 0.f, 0.f};
    float4 v[8];

#define STAGE_GROUP(dst, j) do {                                                \
        uint32_t r0 = cvt_rna_tf32(v[j].x), r1 = cvt_rna_tf32(v[j].y);          \
        uint32_t r2 = cvt_rna_tf32(v[j].z), r3 = cvt_rna_tf32(v[j].w);          \
        s4[0] += __uint_as_float(r0); s4[1] += __uint_as_float(r1);             \
        s4[2] += __uint_as_float(r2); s4[3] += __uint_as_float(r3);             \
        *reinterpret_cast<float4*>(&(dst)[(krow0 + 4 * (j)) * SROW + dq]) =     \
            make_float4(__uint_as_float(r0), __uint_as_float(r1),               \
                        __uint_as_float(r2), __uint_as_float(r3));              \
    } while (0)

    // ---- prologue: stage chunk 0 ----
#pragma unroll
    for (int j = 0; j < 8; ++j) v[j] = gp[j * 256];
#pragma unroll
    for (int j = 0; j < 8; ++j) STAGE_GROUP(buf0, j);
    __syncthreads();

#pragma unroll 1
    for (int c = 0; c < NCHUNK; ++c) {
        const bool more = (c + 1 < NCHUNK);
        const uint32_t* cur =
            reinterpret_cast<const uint32_t*>((c & 1) ? buf1 : buf0);
        float* nxt = (c & 1) ? buf0 : buf1;

        if (more) {
#pragma unroll
            for (int j = 0; j < 8; ++j)
                v[j] = gp[(c + 1) * 2048 + j * 256];
        }

        // staggered unit order between warp groups to break SMSP lockstep
        if (wid < 4) {
#pragma unroll
            for (int ks = 0; ks < 4; ++ks)
                unit_mma(cur, own_m, own_n, ks * 8, acc0, g, tig);
            unit_mma(cur, sh_m, sh_n, sh_k0, acc1, g, tig);
        } else {
            unit_mma(cur, sh_m, sh_n, sh_k0, acc1, g, tig);
#pragma unroll
            for (int ks = 0; ks < 4; ++ks)
                unit_mma(cur, own_m, own_n, ks * 8, acc0, g, tig);
        }

        if (more) {
#pragma unroll
            for (int j = 0; j < 8; ++j) STAGE_GROUP(nxt, j);
        }
        __syncthreads();
    }

    // ---- column sums + shared-tile partials into smem ----
    psum[(tid >> 6) * 256 + dq + 0] = s4[0];
    psum[(tid >> 6) * 256 + dq + 1] = s4[1];
    psum[(tid >> 6) * 256 + dq + 2] = s4[2];
    psum[(tid >> 6) * 256 + dq + 3] = s4[3];

    // stage buffers are dead now: reuse sm[0 .. 16384) for shared partials.
    // region (wid>>2) in {0,1}, copy (wid&3) in {0..3}, 2048 floats each.
    {
        float* shb = sm + (wid >> 2) * 8192 + (wid & 3) * 2048;
#pragma unroll
        for (int mf = 0; mf < 4; ++mf)
#pragma unroll
            for (int nf = 0; nf < 4; ++nf)
#pragma unroll
                for (int cc = 0; cc < 4; ++cc) {
                    const int row = mf * 16 + g + (cc >> 1) * 8;
                    const int col = nf * 8 + 2 * tig + (cc & 1);
                    shb[row * 32 + col] = acc1[mf * 4 + nf][cc];
                }
    }
    __syncthreads();
    csum[tid] = psum[tid] + psum[256 + tid] + psum[512 + tid] + psum[768 + tid];
    __syncthreads();

    const float invN = 1.0f / (float)NPTS;
    const size_t outb = (size_t)b * TRI;

    // ---- own half-tile outputs ----
#pragma unroll
    for (int mf = 0; mf < 4; ++mf)
#pragma unroll
        for (int nf = 0; nf < 4; ++nf)
#pragma unroll
            for (int cc = 0; cc < 4; ++cc) {
                const int d = own_m + mf * 16 + g + (cc >> 1) * 8;
                const int e = own_n + nf * 8 + 2 * tig + (cc & 1);
                if (e >= d) {
                    const float mu_d = csum[d] * invN;
                    const float mu_e = csum[e] * invN;
                    const int idx = d * DIM - (d * (d - 1)) / 2 - d + e;
                    out[outb + (size_t)idx] =
                        acc0[mf * 4 + nf][cc] * invN - mu_d * mu_e;
                }
            }

    // ---- shared half-tile reduction + outputs ----
#pragma unroll
    for (int r = 0; r < 2; ++r) {
        int rmi, rnj;
        ht_mn(2 * (8 + r) + h, rmi, rnj);
        const int d0 = rmi * 64, e0 = rnj * 32;
        const float* base = sm + r * 8192;
#pragma unroll 1
        for (int i = tid; i < 2048; i += 256) {
            float vsum = base[i] + base[2048 + i] + base[4096 + i] +
                         base[6144 + i];
            const int d = d0 + (i >> 5);
            const int e = e0 + (i & 31);
            if (e >= d) {
                const float mu_d = csum[d] * invN;
                const float mu_e = csum[e] * invN;
                const int idx = d * DIM - (d * (d - 1)) / 2 - d + e;
                out[outb + (size_t)idx] = vsum * invN - mu_d * mu_e;
            }
        }
    }
}

extern "C" void kernel_launch(void* const* d_in, const int* in_sizes, int n_in,
                              void* d_out, int out_size)
{
    const float* X = (const float*)d_in[0];
    float* out = (float*)d_out;
    cudaFuncSetAttribute(cov_mma_kernel,
                         cudaFuncAttributeMaxDynamicSharedMemorySize,
                         SMEM_BYTES);
    cov_mma_kernel<<<BATCH * 2, 256, SMEM_BYTES>>>(X, out);
}